// round 5
// baseline (speedup 1.0000x reference)
#include <cuda_runtime.h>
#include <math.h>

#define MAXN 100000
#define NS 16
#define C 64
#define PTS 8          // points per block (processed in pairs)

// Scratch for Q/K/V projections (allocation-free rule: __device__ globals)
__device__ float g_q[MAXN * C];
__device__ float g_k[MAXN * C];
__device__ float g_v[MAXN * C];

// ---------------------------------------------------------------------------
// Kernel 1: QKV projection (R2 version, measured 63.6us). grid=(N/64,3), 256t.
// ---------------------------------------------------------------------------
__global__ void __launch_bounds__(256) qkv_gemm(
    const float* __restrict__ x,
    const float* __restrict__ Wq, const float* __restrict__ bq,
    const float* __restrict__ Wk, const float* __restrict__ bk,
    const float* __restrict__ Wv, const float* __restrict__ bv,
    int N)
{
    __shared__ float xs[64][68];
    __shared__ float ws[64][64];

    const float* W;
    const float* b;
    float* out;
    if (blockIdx.y == 0)      { W = Wq; b = bq; out = g_q; }
    else if (blockIdx.y == 1) { W = Wk; b = bk; out = g_k; }
    else                      { W = Wv; b = bv; out = g_v; }

    const int r0  = blockIdx.x * 64;
    const int tid = threadIdx.x;

    #pragma unroll
    for (int t = 0; t < 4; t++) {
        int i4  = tid + 256 * t;
        int row = i4 >> 4;
        int c4  = (i4 & 15) << 2;
        float4 wv4 = *(const float4*)(W + row * 64 + c4);
        *(float4*)(&ws[row][c4]) = wv4;
        int gr = r0 + row;
        float4 xv4 = (gr < N) ? *(const float4*)(x + (long long)gr * 64 + c4)
                              : make_float4(0.f, 0.f, 0.f, 0.f);
        *(float4*)(&xs[row][c4]) = xv4;
    }
    __syncthreads();

    const int tx = tid & 15;
    const int ty = tid >> 4;

    float4 bias4 = *(const float4*)(b + tx * 4);
    float acc[4][4];
    #pragma unroll
    for (int r = 0; r < 4; r++) {
        acc[r][0] = bias4.x; acc[r][1] = bias4.y;
        acc[r][2] = bias4.z; acc[r][3] = bias4.w;
    }

    #pragma unroll 8
    for (int k = 0; k < 64; k++) {
        float4 w4 = *(const float4*)(&ws[k][tx * 4]);
        float a0 = xs[ty * 4 + 0][k];
        float a1 = xs[ty * 4 + 1][k];
        float a2 = xs[ty * 4 + 2][k];
        float a3 = xs[ty * 4 + 3][k];
        acc[0][0] = fmaf(a0, w4.x, acc[0][0]); acc[0][1] = fmaf(a0, w4.y, acc[0][1]);
        acc[0][2] = fmaf(a0, w4.z, acc[0][2]); acc[0][3] = fmaf(a0, w4.w, acc[0][3]);
        acc[1][0] = fmaf(a1, w4.x, acc[1][0]); acc[1][1] = fmaf(a1, w4.y, acc[1][1]);
        acc[1][2] = fmaf(a1, w4.z, acc[1][2]); acc[1][3] = fmaf(a1, w4.w, acc[1][3]);
        acc[2][0] = fmaf(a2, w4.x, acc[2][0]); acc[2][1] = fmaf(a2, w4.y, acc[2][1]);
        acc[2][2] = fmaf(a2, w4.z, acc[2][2]); acc[2][3] = fmaf(a2, w4.w, acc[2][3]);
        acc[3][0] = fmaf(a3, w4.x, acc[3][0]); acc[3][1] = fmaf(a3, w4.y, acc[3][1]);
        acc[3][2] = fmaf(a3, w4.z, acc[3][2]); acc[3][3] = fmaf(a3, w4.w, acc[3][3]);
    }

    #pragma unroll
    for (int r = 0; r < 4; r++) {
        int gr = r0 + ty * 4 + r;
        if (gr < N) {
            float4 o4 = make_float4(acc[r][0], acc[r][1], acc[r][2], acc[r][3]);
            *(float4*)(out + (long long)gr * 64 + tx * 4) = o4;
        }
    }
}

// ---------------------------------------------------------------------------
// Kernel 2: per-point attention, TWO points per iteration.
// Thread (j = tid>>3, l = tid&7): neighbor j, channels {h*32 + l*4 + m}.
// Weight LDS amortized over the pair; scalar constants hoisted to registers.
// ---------------------------------------------------------------------------
__global__ void __launch_bounds__(128) pt_attn(
    const float* __restrict__ p,
    const int*   __restrict__ idx,
    const float* __restrict__ Wp1, const float* __restrict__ bp1,
    const float* __restrict__ gp,  const float* __restrict__ bpv,
    const float* __restrict__ Wp2, const float* __restrict__ bp2,
    const float* __restrict__ g1,  const float* __restrict__ bb1,
    const float* __restrict__ Wa,  const float* __restrict__ ba,
    const float* __restrict__ g2,  const float* __restrict__ bb2,
    const float* __restrict__ Wb,  const float* __restrict__ bw,
    float* __restrict__ out, int N)
{
    const int tid = threadIdx.x;
    const int wid = tid >> 5;
    const int j   = tid >> 3;     // 0..15
    const int l   = tid & 7;

    __shared__ float  s_Wat[8][68];      // Wa^T [ch][c]
    __shared__ float  s_Wbt[8][12];      // Wb^T [lout][ch]
    __shared__ float  s_Wp2s[3][68];
    __shared__ float  s_bp2[64];
    __shared__ float2 s_s1b1[64];        // {g1*binv, bb1}
    __shared__ float  s_misc[64];        // 0:ba 8:s2 16:b2 24:bw 32:Wp1(9) 41:bp1 44:gp*binv 47:bp
    __shared__ float  s_wraw[2][16][12];
    __shared__ float  s_w[2][16][8];
    __shared__ float  s_part[2][4][68];

    const float bninv = rsqrtf(1.f + 1e-5f);

    for (int t = tid; t < 512; t += 128) s_Wat[t & 7][t >> 3] = __ldg(Wa + t);
    if (tid < 64) {
        s_Wbt[tid & 7][tid >> 3] = __ldg(Wb + tid);
        s_s1b1[tid] = make_float2(__ldg(g1 + tid) * bninv, __ldg(bb1 + tid));
        s_bp2[tid]  = __ldg(bp2 + tid);
    }
    for (int t = tid; t < 192; t += 128) s_Wp2s[t / 64][t % 64] = __ldg(Wp2 + t);
    if (tid < 8) {
        s_misc[tid]      = __ldg(ba + tid);
        s_misc[8 + tid]  = __ldg(g2 + tid) * bninv;
        s_misc[16 + tid] = __ldg(bb2 + tid);
        s_misc[24 + tid] = __ldg(bw + tid);
    }
    if (tid < 9)  s_misc[32 + tid] = __ldg(Wp1 + tid);
    if (tid < 3) {
        s_misc[41 + tid] = __ldg(bp1 + tid);
        s_misc[44 + tid] = __ldg(gp + tid) * bninv;
        s_misc[47 + tid] = __ldg(bpv + tid);
    }
    __syncthreads();

    // hoist block-loop-invariant scalars to registers
    float wp1r[9], bp1r[3], gpir[3], bpr[3];
    #pragma unroll
    for (int o = 0; o < 9; o++) wp1r[o] = s_misc[32 + o];
    #pragma unroll
    for (int o = 0; o < 3; o++) {
        bp1r[o] = s_misc[41 + o];
        gpir[o] = s_misc[44 + o];
        bpr[o]  = s_misc[47 + o];
    }
    const float bn2a = s_misc[l];          // ba[l]
    const float bn2s = s_misc[8 + l];      // s2[l]
    const float bn2b = s_misc[16 + l];     // b2[l]
    const float bwl  = s_misc[24 + l];     // bw[l]
    const float4 wb0 = *(const float4*)&s_Wbt[l][0];
    const float4 wb1 = *(const float4*)&s_Wbt[l][4];

    const int i0 = blockIdx.x * PTS;

    #pragma unroll 1
    for (int it = 0; it < PTS / 2; it++) {
        const int iA = i0 + it * 2;
        const int iB = iA + 1;
        const bool actA = (iA < N);
        const bool actB = (iB < N);

        float valA[8], valB[8], wvA[8], wvB[8];
        float t3A[3], t3B[3];
        int njA = 0, njB = 0;

        if (actA) {
            njA = __ldg(idx + iA * NS + j);
            float rx = __ldg(p + njA * 3 + 0) - __ldg(p + iA * 3 + 0);
            float ry = __ldg(p + njA * 3 + 1) - __ldg(p + iA * 3 + 1);
            float rz = __ldg(p + njA * 3 + 2) - __ldg(p + iA * 3 + 2);
            #pragma unroll
            for (int o = 0; o < 3; o++) {
                float u = fmaf(rx, wp1r[o], fmaf(ry, wp1r[3 + o], fmaf(rz, wp1r[6 + o], bp1r[o])));
                t3A[o] = fmaxf(fmaf(u, gpir[o], bpr[o]), 0.f);
            }
        }
        if (actB) {
            njB = __ldg(idx + iB * NS + j);
            float rx = __ldg(p + njB * 3 + 0) - __ldg(p + iB * 3 + 0);
            float ry = __ldg(p + njB * 3 + 1) - __ldg(p + iB * 3 + 1);
            float rz = __ldg(p + njB * 3 + 2) - __ldg(p + iB * 3 + 2);
            #pragma unroll
            for (int o = 0; o < 3; o++) {
                float u = fmaf(rx, wp1r[o], fmaf(ry, wp1r[3 + o], fmaf(rz, wp1r[6 + o], bp1r[o])));
                t3B[o] = fmaxf(fmaf(u, gpir[o], bpr[o]), 0.f);
            }
        }

        #pragma unroll
        for (int h = 0; h < 2; h++) {
            const int c0 = h * 32 + l * 4;
            // weights loaded ONCE for the pair
            float4 w0 = *(const float4*)&s_Wp2s[0][c0];
            float4 w1 = *(const float4*)&s_Wp2s[1][c0];
            float4 w2 = *(const float4*)&s_Wp2s[2][c0];
            float4 b2 = *(const float4*)&s_bp2[c0];
            float4 sb01 = *(const float4*)&s_s1b1[c0];
            float4 sb23 = *(const float4*)&s_s1b1[c0 + 2];

            if (actA) {
                float4 q4 = __ldg((const float4*)(g_q + (long long)iA  * 64 + c0));
                float4 k4 = __ldg((const float4*)(g_k + (long long)njA * 64 + c0));
                float4 v4 = __ldg((const float4*)(g_v + (long long)njA * 64 + c0));
                float pe0 = fmaf(t3A[0], w0.x, fmaf(t3A[1], w1.x, fmaf(t3A[2], w2.x, b2.x)));
                float pe1 = fmaf(t3A[0], w0.y, fmaf(t3A[1], w1.y, fmaf(t3A[2], w2.y, b2.y)));
                float pe2 = fmaf(t3A[0], w0.z, fmaf(t3A[1], w1.z, fmaf(t3A[2], w2.z, b2.z)));
                float pe3 = fmaf(t3A[0], w0.w, fmaf(t3A[1], w1.w, fmaf(t3A[2], w2.w, b2.w)));
                valA[h*4+0] = v4.x + pe0; valA[h*4+1] = v4.y + pe1;
                valA[h*4+2] = v4.z + pe2; valA[h*4+3] = v4.w + pe3;
                wvA[h*4+0] = fmaxf(fmaf(k4.x - q4.x + pe0, sb01.x, sb01.y), 0.f);
                wvA[h*4+1] = fmaxf(fmaf(k4.y - q4.y + pe1, sb01.z, sb01.w), 0.f);
                wvA[h*4+2] = fmaxf(fmaf(k4.z - q4.z + pe2, sb23.x, sb23.y), 0.f);
                wvA[h*4+3] = fmaxf(fmaf(k4.w - q4.w + pe3, sb23.z, sb23.w), 0.f);
            }
            if (actB) {
                float4 q4 = __ldg((const float4*)(g_q + (long long)iB  * 64 + c0));
                float4 k4 = __ldg((const float4*)(g_k + (long long)njB * 64 + c0));
                float4 v4 = __ldg((const float4*)(g_v + (long long)njB * 64 + c0));
                float pe0 = fmaf(t3B[0], w0.x, fmaf(t3B[1], w1.x, fmaf(t3B[2], w2.x, b2.x)));
                float pe1 = fmaf(t3B[0], w0.y, fmaf(t3B[1], w1.y, fmaf(t3B[2], w2.y, b2.y)));
                float pe2 = fmaf(t3B[0], w0.z, fmaf(t3B[1], w1.z, fmaf(t3B[2], w2.z, b2.z)));
                float pe3 = fmaf(t3B[0], w0.w, fmaf(t3B[1], w1.w, fmaf(t3B[2], w2.w, b2.w)));
                valB[h*4+0] = v4.x + pe0; valB[h*4+1] = v4.y + pe1;
                valB[h*4+2] = v4.z + pe2; valB[h*4+3] = v4.w + pe3;
                wvB[h*4+0] = fmaxf(fmaf(k4.x - q4.x + pe0, sb01.x, sb01.y), 0.f);
                wvB[h*4+1] = fmaxf(fmaf(k4.y - q4.y + pe1, sb01.z, sb01.w), 0.f);
                wvB[h*4+2] = fmaxf(fmaf(k4.z - q4.z + pe2, sb23.x, sb23.y), 0.f);
                wvB[h*4+3] = fmaxf(fmaf(k4.w - q4.w + pe3, sb23.z, sb23.w), 0.f);
            }
        }

        // y[ch] partials over this thread's 8 c's; Wa rows loaded once per ch
        float yA[8], yB[8];
        #pragma unroll
        for (int ch = 0; ch < 8; ch++) {
            float4 a0 = *(const float4*)&s_Wat[ch][l * 4];
            float4 a1 = *(const float4*)&s_Wat[ch][32 + l * 4];
            float tA = 0.f, tB = 0.f;
            tA = fmaf(wvA[0], a0.x, tA); tB = fmaf(wvB[0], a0.x, tB);
            tA = fmaf(wvA[1], a0.y, tA); tB = fmaf(wvB[1], a0.y, tB);
            tA = fmaf(wvA[2], a0.z, tA); tB = fmaf(wvB[2], a0.z, tB);
            tA = fmaf(wvA[3], a0.w, tA); tB = fmaf(wvB[3], a0.w, tB);
            tA = fmaf(wvA[4], a1.x, tA); tB = fmaf(wvB[4], a1.x, tB);
            tA = fmaf(wvA[5], a1.y, tA); tB = fmaf(wvB[5], a1.y, tB);
            tA = fmaf(wvA[6], a1.z, tA); tB = fmaf(wvB[6], a1.z, tB);
            tA = fmaf(wvA[7], a1.w, tA); tB = fmaf(wvB[7], a1.w, tB);
            yA[ch] = tA; yB[ch] = tB;
        }
        #pragma unroll
        for (int off = 1; off < 8; off <<= 1) {
            #pragma unroll
            for (int ch = 0; ch < 8; ch++) {
                yA[ch] += __shfl_xor_sync(0xffffffffu, yA[ch], off);
                yB[ch] += __shfl_xor_sync(0xffffffffu, yB[ch], off);
            }
        }

        // BN2 + ReLU + Wb -> score channel l (per point)
        {
            float scA = bwl, scB = bwl;
            #pragma unroll
            for (int ch = 0; ch < 8; ch++) {
                float wbc = (ch < 4) ? ((ch == 0) ? wb0.x : (ch == 1) ? wb0.y : (ch == 2) ? wb0.z : wb0.w)
                                     : ((ch == 4) ? wb1.x : (ch == 5) ? wb1.y : (ch == 6) ? wb1.z : wb1.w);
                float s2c = s_misc[8 + ch], b2c = s_misc[16 + ch], bac = s_misc[ch];
                float aA = fmaxf(fmaf(yA[ch] + bac, s2c, b2c), 0.f);
                float aB = fmaxf(fmaf(yB[ch] + bac, s2c, b2c), 0.f);
                scA = fmaf(aA, wbc, scA);
                scB = fmaf(aB, wbc, scB);
            }
            if (actA) s_wraw[0][j][l] = scA;
            if (actB) s_wraw[1][j][l] = scB;
        }
        __syncthreads();

        // softmax: threads 0-7 point A, threads 8-15 point B
        if (tid < 16) {
            const int ab = tid >> 3;
            const int ch = tid & 7;
            if ((ab == 0 && actA) || (ab == 1 && actB)) {
                float mx = -1e30f;
                #pragma unroll
                for (int jj = 0; jj < NS; jj++) mx = fmaxf(mx, s_wraw[ab][jj][ch]);
                float sm = 0.f;
                #pragma unroll
                for (int jj = 0; jj < NS; jj++) sm += __expf(s_wraw[ab][jj][ch] - mx);
                float inv = 1.f / sm;
                #pragma unroll
                for (int jj = 0; jj < NS; jj++)
                    s_w[ab][jj][ch] = __expf(s_wraw[ab][jj][ch] - mx) * inv;
            }
        }
        __syncthreads();

        // aggregation in registers; weight loaded once per point
        {
            const int lsel = (l & 1) * 4;
            if (actA) {
                float4 w4 = *(const float4*)&s_w[0][j][lsel];
                float c0v[4], c1v[4];
                c0v[0] = valA[0] * w4.x; c0v[1] = valA[1] * w4.y;
                c0v[2] = valA[2] * w4.z; c0v[3] = valA[3] * w4.w;
                c1v[0] = valA[4] * w4.x; c1v[1] = valA[5] * w4.y;
                c1v[2] = valA[6] * w4.z; c1v[3] = valA[7] * w4.w;
                #pragma unroll
                for (int off = 8; off <= 16; off <<= 1) {
                    #pragma unroll
                    for (int q = 0; q < 4; q++) {
                        c0v[q] += __shfl_xor_sync(0xffffffffu, c0v[q], off);
                        c1v[q] += __shfl_xor_sync(0xffffffffu, c1v[q], off);
                    }
                }
                if ((tid & 24) == 0) {
                    *(float4*)&s_part[0][wid][l * 4]      = make_float4(c0v[0], c0v[1], c0v[2], c0v[3]);
                    *(float4*)&s_part[0][wid][32 + l * 4] = make_float4(c1v[0], c1v[1], c1v[2], c1v[3]);
                }
            }
            if (actB) {
                float4 w4 = *(const float4*)&s_w[1][j][lsel];
                float c0v[4], c1v[4];
                c0v[0] = valB[0] * w4.x; c0v[1] = valB[1] * w4.y;
                c0v[2] = valB[2] * w4.z; c0v[3] = valB[3] * w4.w;
                c1v[0] = valB[4] * w4.x; c1v[1] = valB[5] * w4.y;
                c1v[2] = valB[6] * w4.z; c1v[3] = valB[7] * w4.w;
                #pragma unroll
                for (int off = 8; off <= 16; off <<= 1) {
                    #pragma unroll
                    for (int q = 0; q < 4; q++) {
                        c0v[q] += __shfl_xor_sync(0xffffffffu, c0v[q], off);
                        c1v[q] += __shfl_xor_sync(0xffffffffu, c1v[q], off);
                    }
                }
                if ((tid & 24) == 0) {
                    *(float4*)&s_part[1][wid][l * 4]      = make_float4(c0v[0], c0v[1], c0v[2], c0v[3]);
                    *(float4*)&s_part[1][wid][32 + l * 4] = make_float4(c1v[0], c1v[1], c1v[2], c1v[3]);
                }
            }
        }
        __syncthreads();

        if (tid < 64) {
            if (actA) {
                float o = s_part[0][0][tid] + s_part[0][1][tid]
                        + s_part[0][2][tid] + s_part[0][3][tid];
                out[(long long)iA * 64 + tid] = o;
            }
        } else {
            const int t = tid - 64;
            if (actB) {
                float o = s_part[1][0][t] + s_part[1][1][t]
                        + s_part[1][2][t] + s_part[1][3][t];
                out[(long long)iB * 64 + t] = o;
            }
        }
        __syncthreads();
    }
}

// ---------------------------------------------------------------------------
extern "C" void kernel_launch(void* const* d_in, const int* in_sizes, int n_in,
                              void* d_out, int out_size)
{
    const float* p   = (const float*)d_in[0];
    const float* x   = (const float*)d_in[1];
    const int*   idx = (const int*)  d_in[2];
    const float* Wq  = (const float*)d_in[3];
    const float* bq  = (const float*)d_in[4];
    const float* Wk  = (const float*)d_in[5];
    const float* bk  = (const float*)d_in[6];
    const float* Wv  = (const float*)d_in[7];
    const float* bv  = (const float*)d_in[8];
    const float* Wp1 = (const float*)d_in[9];
    const float* bp1 = (const float*)d_in[10];
    const float* gp  = (const float*)d_in[11];
    const float* bpv = (const float*)d_in[12];
    const float* Wp2 = (const float*)d_in[13];
    const float* bp2 = (const float*)d_in[14];
    const float* g1  = (const float*)d_in[15];
    const float* bb1 = (const float*)d_in[16];
    const float* Wa  = (const float*)d_in[17];
    const float* ba  = (const float*)d_in[18];
    const float* g2  = (const float*)d_in[19];
    const float* bb2 = (const float*)d_in[20];
    const float* Wb  = (const float*)d_in[21];
    const float* bw  = (const float*)d_in[22];
    float* out = (float*)d_out;

    int N = in_sizes[1] / C;
    if (N > MAXN) N = MAXN;

    dim3 gridA((N + 63) / 64, 3);
    qkv_gemm<<<gridA, 256>>>(x, Wq, bq, Wk, bk, Wv, bv, N);

    pt_attn<<<(N + PTS - 1) / PTS, 128>>>(p, idx, Wp1, bp1, gp, bpv, Wp2, bp2,
                                          g1, bb1, Wa, ba, g2, bb2, Wb, bw, out, N);
}

// round 9
// speedup vs baseline: 2.1061x; 2.1061x over previous
#include <cuda_runtime.h>
#include <cuda_fp16.h>
#include <math.h>

#define MAXN 100000
#define NS 16
#define C 64
#define PTS 8          // points per block (sequential)

// fp16 scratch for Q/K/V projections (allocation-free rule: __device__ globals)
__device__ __half g_qh[MAXN * C];
__device__ __half g_kh[MAXN * C];
__device__ __half g_vh[MAXN * C];

// ---------------------------------------------------------------------------
// Kernel 1: QKV projection, fp32 math, fp16 outputs. grid=(N/64,3), 256t.
// ---------------------------------------------------------------------------
__global__ void __launch_bounds__(256) qkv_gemm(
    const float* __restrict__ x,
    const float* __restrict__ Wq, const float* __restrict__ bq,
    const float* __restrict__ Wk, const float* __restrict__ bk,
    const float* __restrict__ Wv, const float* __restrict__ bv,
    int N)
{
    __shared__ float xs[64][68];
    __shared__ float ws[64][64];

    const float* W;
    const float* b;
    __half* out;
    if (blockIdx.y == 0)      { W = Wq; b = bq; out = g_qh; }
    else if (blockIdx.y == 1) { W = Wk; b = bk; out = g_kh; }
    else                      { W = Wv; b = bv; out = g_vh; }

    const int r0  = blockIdx.x * 64;
    const int tid = threadIdx.x;

    #pragma unroll
    for (int t = 0; t < 4; t++) {
        int i4  = tid + 256 * t;
        int row = i4 >> 4;
        int c4  = (i4 & 15) << 2;
        float4 wv4 = *(const float4*)(W + row * 64 + c4);
        *(float4*)(&ws[row][c4]) = wv4;
        int gr = r0 + row;
        float4 xv4 = (gr < N) ? *(const float4*)(x + (long long)gr * 64 + c4)
                              : make_float4(0.f, 0.f, 0.f, 0.f);
        *(float4*)(&xs[row][c4]) = xv4;
    }
    __syncthreads();

    const int tx = tid & 15;
    const int ty = tid >> 4;

    float4 bias4 = *(const float4*)(b + tx * 4);
    float acc[4][4];
    #pragma unroll
    for (int r = 0; r < 4; r++) {
        acc[r][0] = bias4.x; acc[r][1] = bias4.y;
        acc[r][2] = bias4.z; acc[r][3] = bias4.w;
    }

    #pragma unroll 8
    for (int k = 0; k < 64; k++) {
        float4 w4 = *(const float4*)(&ws[k][tx * 4]);
        float a0 = xs[ty * 4 + 0][k];
        float a1 = xs[ty * 4 + 1][k];
        float a2 = xs[ty * 4 + 2][k];
        float a3 = xs[ty * 4 + 3][k];
        acc[0][0] = fmaf(a0, w4.x, acc[0][0]); acc[0][1] = fmaf(a0, w4.y, acc[0][1]);
        acc[0][2] = fmaf(a0, w4.z, acc[0][2]); acc[0][3] = fmaf(a0, w4.w, acc[0][3]);
        acc[1][0] = fmaf(a1, w4.x, acc[1][0]); acc[1][1] = fmaf(a1, w4.y, acc[1][1]);
        acc[1][2] = fmaf(a1, w4.z, acc[1][2]); acc[1][3] = fmaf(a1, w4.w, acc[1][3]);
        acc[2][0] = fmaf(a2, w4.x, acc[2][0]); acc[2][1] = fmaf(a2, w4.y, acc[2][1]);
        acc[2][2] = fmaf(a2, w4.z, acc[2][2]); acc[2][3] = fmaf(a2, w4.w, acc[2][3]);
        acc[3][0] = fmaf(a3, w4.x, acc[3][0]); acc[3][1] = fmaf(a3, w4.y, acc[3][1]);
        acc[3][2] = fmaf(a3, w4.z, acc[3][2]); acc[3][3] = fmaf(a3, w4.w, acc[3][3]);
    }

    #pragma unroll
    for (int r = 0; r < 4; r++) {
        int gr = r0 + ty * 4 + r;
        if (gr < N) {
            __half2 h01 = __floats2half2_rn(acc[r][0], acc[r][1]);
            __half2 h23 = __floats2half2_rn(acc[r][2], acc[r][3]);
            __half2* op = reinterpret_cast<__half2*>(out + (long long)gr * 64 + tx * 4);
            op[0] = h01; op[1] = h23;
        }
    }
}

// ---------------------------------------------------------------------------
// Kernel 2: per-point attention. 128 threads, PTS points sequential.
// Thread (j = tid>>3, l = tid&7): neighbor j, channels c = l*8 .. l*8+7.
// fp16 gathers (1 LDG.128 covers a full row) + fp16 weights in smem.
// ---------------------------------------------------------------------------
__global__ void __launch_bounds__(128) pt_attn(
    const float* __restrict__ p,
    const int*   __restrict__ idx,
    const float* __restrict__ Wp1, const float* __restrict__ bp1,
    const float* __restrict__ gp,  const float* __restrict__ bpv,
    const float* __restrict__ Wp2, const float* __restrict__ bp2,
    const float* __restrict__ g1,  const float* __restrict__ bb1,
    const float* __restrict__ Wa,  const float* __restrict__ ba,
    const float* __restrict__ g2,  const float* __restrict__ bb2,
    const float* __restrict__ Wb,  const float* __restrict__ bw,
    float* __restrict__ out, int N)
{
    const int tid = threadIdx.x;
    const int wid = tid >> 5;
    const int j   = tid >> 3;     // 0..15
    const int l   = tid & 7;

    // fp16 weights, bank-safe padded strides (pad word-count not ≡ 0 mod 32)
    __shared__ __half s_WaH[8][72];    // [l][r*8+ch] = Wa[(l*8+r)*8+ch]; 144B stride
    __shared__ __half s_peH[8][40];    // [l][{W0,W1,W2,B2} x 8]; 80B stride
    __shared__ __half s_sbH[8][24];    // [l][{s1 x8, b1 x8}]; 48B stride
    __shared__ float  s_Wbt[8][12];    // Wb^T [lout][ch]
    __shared__ float  s_misc[64];      // 0:ba 8:s2 16:b2 24:bw 32:Wp1(9) 41:bp1 44:gp*binv 47:bp
    __shared__ float  s_wraw[16][12];
    __shared__ float  s_w[16][8];
    __shared__ float  s_part[4][72];

    const float bninv = rsqrtf(1.f + 1e-5f);

    // stage weights (once per block)
    for (int t = tid; t < 512; t += 128) {
        int c = t >> 3, ch = t & 7;
        s_WaH[c >> 3][(c & 7) * 8 + ch] = __float2half(__ldg(Wa + t));
    }
    if (tid < 64) {
        int ll = tid >> 3, m = tid & 7;
        int c = ll * 8 + m;
        s_peH[ll][0  + m] = __float2half(__ldg(Wp2 + c));
        s_peH[ll][8  + m] = __float2half(__ldg(Wp2 + 64 + c));
        s_peH[ll][16 + m] = __float2half(__ldg(Wp2 + 128 + c));
        s_peH[ll][24 + m] = __float2half(__ldg(bp2 + c));
        s_sbH[ll][m]      = __float2half(__ldg(g1 + c) * bninv);
        s_sbH[ll][8 + m]  = __float2half(__ldg(bb1 + c));
        s_Wbt[tid & 7][tid >> 3] = __ldg(Wb + tid);
    }
    if (tid < 8) {
        s_misc[tid]      = __ldg(ba + tid);
        s_misc[8 + tid]  = __ldg(g2 + tid) * bninv;
        s_misc[16 + tid] = __ldg(bb2 + tid);
        s_misc[24 + tid] = __ldg(bw + tid);
    }
    if (tid < 9)  s_misc[32 + tid] = __ldg(Wp1 + tid);
    if (tid < 3) {
        s_misc[41 + tid] = __ldg(bp1 + tid);
        s_misc[44 + tid] = __ldg(gp + tid) * bninv;
        s_misc[47 + tid] = __ldg(bpv + tid);
    }
    __syncthreads();

    const int i0 = blockIdx.x * PTS;

    #pragma unroll 1
    for (int it = 0; it < PTS; it++) {
        const int i = i0 + it;
        const bool act = (i < N);            // uniform across block

        float val[8];

        if (act) {
            const int nj = __ldg(idx + i * NS + j);
            const float rx = __ldg(p + nj * 3 + 0) - __ldg(p + i * 3 + 0);
            const float ry = __ldg(p + nj * 3 + 1) - __ldg(p + i * 3 + 1);
            const float rz = __ldg(p + nj * 3 + 2) - __ldg(p + i * 3 + 2);
            float t3[3];
            #pragma unroll
            for (int o = 0; o < 3; o++) {
                float u = fmaf(rx, s_misc[32 + o],
                          fmaf(ry, s_misc[35 + o],
                          fmaf(rz, s_misc[38 + o], s_misc[41 + o])));
                t3[o] = fmaxf(fmaf(u, s_misc[44 + o], s_misc[47 + o]), 0.f);
            }
            __half2 t0h = __float2half2_rn(t3[0]);
            __half2 t1h = __float2half2_rn(t3[1]);
            __half2 t2h = __float2half2_rn(t3[2]);

            // one LDG.128 each: full fp16 8-channel chunk
            uint4 qr = *reinterpret_cast<const uint4*>(g_qh + (long long)i  * 64 + l * 8);
            uint4 kr = *reinterpret_cast<const uint4*>(g_kh + (long long)nj * 64 + l * 8);
            uint4 vr = *reinterpret_cast<const uint4*>(g_vh + (long long)nj * 64 + l * 8);

            const uint4* peL = reinterpret_cast<const uint4*>(&s_peH[l][0]);
            uint4 W0 = peL[0], W1 = peL[1], W2 = peL[2], B2 = peL[3];
            const uint4* sbL = reinterpret_cast<const uint4*>(&s_sbH[l][0]);
            uint4 S1 = sbL[0], B1 = sbL[1];

            float wv[8];
            const unsigned* qp = &qr.x;
            const unsigned* kp = &kr.x;
            const unsigned* vp = &vr.x;
            const unsigned* w0p = &W0.x; const unsigned* w1p = &W1.x;
            const unsigned* w2p = &W2.x; const unsigned* b2p = &B2.x;
            const unsigned* s1p = &S1.x; const unsigned* b1p = &B1.x;

            #pragma unroll
            for (int pp = 0; pp < 4; pp++) {
                __half2 pe2 = __hfma2(t0h, *(const __half2*)&w0p[pp],
                              __hfma2(t1h, *(const __half2*)&w1p[pp],
                              __hfma2(t2h, *(const __half2*)&w2p[pp],
                                      *(const __half2*)&b2p[pp])));
                float2 pef = __half22float2(pe2);
                float2 vf  = __half22float2(*(const __half2*)&vp[pp]);
                val[2*pp]   = vf.x + pef.x;
                val[2*pp+1] = vf.y + pef.y;
                __half2 d2 = __hsub2(*(const __half2*)&kp[pp], *(const __half2*)&qp[pp]);
                float2 df = __half22float2(d2);
                float2 s1f = __half22float2(*(const __half2*)&s1p[pp]);
                float2 b1f = __half22float2(*(const __half2*)&b1p[pp]);
                wv[2*pp]   = fmaxf(fmaf(df.x + pef.x, s1f.x, b1f.x), 0.f);
                wv[2*pp+1] = fmaxf(fmaf(df.y + pef.y, s1f.y, b1f.y), 0.f);
            }

            // y[ch] = sum over this thread's 8 c's (HFMA2 partials, 8 terms)
            __half2 wv2[4];
            #pragma unroll
            for (int pp = 0; pp < 4; pp++)
                wv2[pp] = __floats2half2_rn(wv[2*pp], wv[2*pp+1]);
            __half2 y2[4];
            y2[0] = y2[1] = y2[2] = y2[3] = __float2half2_rn(0.f);
            const uint4* waL = reinterpret_cast<const uint4*>(&s_WaH[l][0]);
            #pragma unroll
            for (int r = 0; r < 8; r++) {
                uint4 wa = waL[r];
                const unsigned* wap = &wa.x;
                __half2 wb2 = (r & 1) ? __high2half2(wv2[r >> 1])
                                      : __low2half2(wv2[r >> 1]);
                y2[0] = __hfma2(wb2, *(const __half2*)&wap[0], y2[0]);
                y2[1] = __hfma2(wb2, *(const __half2*)&wap[1], y2[1]);
                y2[2] = __hfma2(wb2, *(const __half2*)&wap[2], y2[2]);
                y2[3] = __hfma2(wb2, *(const __half2*)&wap[3], y2[3]);
            }
            float y[8];
            #pragma unroll
            for (int pp = 0; pp < 4; pp++) {
                float2 f = __half22float2(y2[pp]);
                y[2*pp] = f.x; y[2*pp+1] = f.y;
            }
            // reduce over the 8 lanes of the j-group (fp32)
            #pragma unroll
            for (int off = 1; off < 8; off <<= 1) {
                #pragma unroll
                for (int ch = 0; ch < 8; ch++)
                    y[ch] += __shfl_xor_sync(0xffffffffu, y[ch], off);
            }

            // BN2 + ReLU + Wb -> score channel l
            float a[8];
            #pragma unroll
            for (int ch = 0; ch < 8; ch++)
                a[ch] = fmaxf(fmaf(y[ch] + s_misc[ch], s_misc[8 + ch], s_misc[16 + ch]), 0.f);
            float4 wb0 = *(const float4*)&s_Wbt[l][0];
            float4 wb1 = *(const float4*)&s_Wbt[l][4];
            float sc = s_misc[24 + l];
            sc = fmaf(a[0], wb0.x, sc); sc = fmaf(a[1], wb0.y, sc);
            sc = fmaf(a[2], wb0.z, sc); sc = fmaf(a[3], wb0.w, sc);
            sc = fmaf(a[4], wb1.x, sc); sc = fmaf(a[5], wb1.y, sc);
            sc = fmaf(a[6], wb1.z, sc); sc = fmaf(a[7], wb1.w, sc);
            s_wraw[j][l] = sc;
        }
        __syncthreads();

        if (act && tid < 8) {
            float mx = -1e30f;
            #pragma unroll
            for (int jj = 0; jj < NS; jj++) mx = fmaxf(mx, s_wraw[jj][tid]);
            float sm = 0.f;
            #pragma unroll
            for (int jj = 0; jj < NS; jj++) sm += __expf(s_wraw[jj][tid] - mx);
            float inv = 1.f / sm;
            #pragma unroll
            for (int jj = 0; jj < NS; jj++)
                s_w[jj][tid] = __expf(s_wraw[jj][tid] - mx) * inv;
        }
        __syncthreads();

        if (act) {
            // channel c = l*8+m uses w[j][m] -> full w row (broadcast per j-group)
            float4 w4a = *(const float4*)&s_w[j][0];
            float4 w4b = *(const float4*)&s_w[j][4];
            float c0v[4], c1v[4];
            c0v[0] = val[0] * w4a.x; c0v[1] = val[1] * w4a.y;
            c0v[2] = val[2] * w4a.z; c0v[3] = val[3] * w4a.w;
            c1v[0] = val[4] * w4b.x; c1v[1] = val[5] * w4b.y;
            c1v[2] = val[6] * w4b.z; c1v[3] = val[7] * w4b.w;
            // reduce over the 4 in-warp neighbors (lane bits 3,4)
            #pragma unroll
            for (int off = 8; off <= 16; off <<= 1) {
                #pragma unroll
                for (int q = 0; q < 4; q++) {
                    c0v[q] += __shfl_xor_sync(0xffffffffu, c0v[q], off);
                    c1v[q] += __shfl_xor_sync(0xffffffffu, c1v[q], off);
                }
            }
            if ((tid & 24) == 0) {   // one lane per (warp, l)
                *(float4*)&s_part[wid][l * 8]     = make_float4(c0v[0], c0v[1], c0v[2], c0v[3]);
                *(float4*)&s_part[wid][l * 8 + 4] = make_float4(c1v[0], c1v[1], c1v[2], c1v[3]);
            }
        }
        __syncthreads();

        if (act && tid < 64) {
            float o = s_part[0][tid] + s_part[1][tid] + s_part[2][tid] + s_part[3][tid];
            out[(long long)i * 64 + tid] = o;
        }
    }
}

// ---------------------------------------------------------------------------
extern "C" void kernel_launch(void* const* d_in, const int* in_sizes, int n_in,
                              void* d_out, int out_size)
{
    const float* p   = (const float*)d_in[0];
    const float* x   = (const float*)d_in[1];
    const int*   idx = (const int*)  d_in[2];
    const float* Wq  = (const float*)d_in[3];
    const float* bq  = (const float*)d_in[4];
    const float* Wk  = (const float*)d_in[5];
    const float* bk  = (const float*)d_in[6];
    const float* Wv  = (const float*)d_in[7];
    const float* bv  = (const float*)d_in[8];
    const float* Wp1 = (const float*)d_in[9];
    const float* bp1 = (const float*)d_in[10];
    const float* gp  = (const float*)d_in[11];
    const float* bpv = (const float*)d_in[12];
    const float* Wp2 = (const float*)d_in[13];
    const float* bp2 = (const float*)d_in[14];
    const float* g1  = (const float*)d_in[15];
    const float* bb1 = (const float*)d_in[16];
    const float* Wa  = (const float*)d_in[17];
    const float* ba  = (const float*)d_in[18];
    const float* g2  = (const float*)d_in[19];
    const float* bb2 = (const float*)d_in[20];
    const float* Wb  = (const float*)d_in[21];
    const float* bw  = (const float*)d_in[22];
    float* out = (float*)d_out;

    int N = in_sizes[1] / C;
    if (N > MAXN) N = MAXN;

    dim3 gridA((N + 63) / 64, 3);
    qkv_gemm<<<gridA, 256>>>(x, Wq, bq, Wk, bk, Wv, bv, N);

    pt_attn<<<(N + PTS - 1) / PTS, 128>>>(p, idx, Wp1, bp1, gp, bpv, Wp2, bp2,
                                          g1, bb1, Wa, ba, g2, bb2, Wb, bw, out, N);
}

// round 10
// speedup vs baseline: 2.2854x; 1.0851x over previous
#include <cuda_runtime.h>
#include <cuda_fp16.h>
#include <math.h>

#define MAXN 100000
#define NS 16
#define C 64
#define PTS 8          // points per block (sequential)

// fp16 scratch for Q/K/V projections + packed positions
__device__ __half g_qh[MAXN * C];
__device__ __half g_kh[MAXN * C];
__device__ __half g_vh[MAXN * C];
__device__ float4 g_p4[MAXN];

// ---------------------------------------------------------------------------
// Kernel 0: pack p[N,3] -> float4 (enables 1-LDG.128 position gathers)
// ---------------------------------------------------------------------------
__global__ void __launch_bounds__(256) pack_p4(const float* __restrict__ p, int N)
{
    int i = blockIdx.x * 256 + threadIdx.x;
    if (i < N) {
        g_p4[i] = make_float4(__ldg(p + i * 3 + 0), __ldg(p + i * 3 + 1),
                              __ldg(p + i * 3 + 2), 0.f);
    }
}

// ---------------------------------------------------------------------------
// Kernel 1: QKV projection, fp32 math, fp16 outputs. grid=(N/64,3), 256t.
// ---------------------------------------------------------------------------
__global__ void __launch_bounds__(256) qkv_gemm(
    const float* __restrict__ x,
    const float* __restrict__ Wq, const float* __restrict__ bq,
    const float* __restrict__ Wk, const float* __restrict__ bk,
    const float* __restrict__ Wv, const float* __restrict__ bv,
    int N)
{
    __shared__ float xs[64][68];
    __shared__ float ws[64][64];

    const float* W;
    const float* b;
    __half* out;
    if (blockIdx.y == 0)      { W = Wq; b = bq; out = g_qh; }
    else if (blockIdx.y == 1) { W = Wk; b = bk; out = g_kh; }
    else                      { W = Wv; b = bv; out = g_vh; }

    const int r0  = blockIdx.x * 64;
    const int tid = threadIdx.x;

    #pragma unroll
    for (int t = 0; t < 4; t++) {
        int i4  = tid + 256 * t;
        int row = i4 >> 4;
        int c4  = (i4 & 15) << 2;
        float4 wv4 = *(const float4*)(W + row * 64 + c4);
        *(float4*)(&ws[row][c4]) = wv4;
        int gr = r0 + row;
        float4 xv4 = (gr < N) ? *(const float4*)(x + (long long)gr * 64 + c4)
                              : make_float4(0.f, 0.f, 0.f, 0.f);
        *(float4*)(&xs[row][c4]) = xv4;
    }
    __syncthreads();

    const int tx = tid & 15;
    const int ty = tid >> 4;

    float4 bias4 = *(const float4*)(b + tx * 4);
    float acc[4][4];
    #pragma unroll
    for (int r = 0; r < 4; r++) {
        acc[r][0] = bias4.x; acc[r][1] = bias4.y;
        acc[r][2] = bias4.z; acc[r][3] = bias4.w;
    }

    #pragma unroll 8
    for (int k = 0; k < 64; k++) {
        float4 w4 = *(const float4*)(&ws[k][tx * 4]);
        float a0 = xs[ty * 4 + 0][k];
        float a1 = xs[ty * 4 + 1][k];
        float a2 = xs[ty * 4 + 2][k];
        float a3 = xs[ty * 4 + 3][k];
        acc[0][0] = fmaf(a0, w4.x, acc[0][0]); acc[0][1] = fmaf(a0, w4.y, acc[0][1]);
        acc[0][2] = fmaf(a0, w4.z, acc[0][2]); acc[0][3] = fmaf(a0, w4.w, acc[0][3]);
        acc[1][0] = fmaf(a1, w4.x, acc[1][0]); acc[1][1] = fmaf(a1, w4.y, acc[1][1]);
        acc[1][2] = fmaf(a1, w4.z, acc[1][2]); acc[1][3] = fmaf(a1, w4.w, acc[1][3]);
        acc[2][0] = fmaf(a2, w4.x, acc[2][0]); acc[2][1] = fmaf(a2, w4.y, acc[2][1]);
        acc[2][2] = fmaf(a2, w4.z, acc[2][2]); acc[2][3] = fmaf(a2, w4.w, acc[2][3]);
        acc[3][0] = fmaf(a3, w4.x, acc[3][0]); acc[3][1] = fmaf(a3, w4.y, acc[3][1]);
        acc[3][2] = fmaf(a3, w4.z, acc[3][2]); acc[3][3] = fmaf(a3, w4.w, acc[3][3]);
    }

    #pragma unroll
    for (int r = 0; r < 4; r++) {
        int gr = r0 + ty * 4 + r;
        if (gr < N) {
            __half2 h01 = __floats2half2_rn(acc[r][0], acc[r][1]);
            __half2 h23 = __floats2half2_rn(acc[r][2], acc[r][3]);
            __half2* op = reinterpret_cast<__half2*>(out + (long long)gr * 64 + tx * 4);
            op[0] = h01; op[1] = h23;
        }
    }
}

// ---------------------------------------------------------------------------
// Kernel 2: per-point attention. 128 threads, PTS points sequential.
// Thread (j = tid>>3, l = tid&7): neighbor j, channels c = l*8 .. l*8+7.
// Reduce-scatter/allgather shuffle patterns; fp16 gathers + fp16 weights.
// ---------------------------------------------------------------------------
__global__ void __launch_bounds__(128) pt_attn(
    const float* __restrict__ p,
    const int*   __restrict__ idx,
    const float* __restrict__ Wp1, const float* __restrict__ bp1,
    const float* __restrict__ gp,  const float* __restrict__ bpv,
    const float* __restrict__ Wp2, const float* __restrict__ bp2,
    const float* __restrict__ g1,  const float* __restrict__ bb1,
    const float* __restrict__ Wa,  const float* __restrict__ ba,
    const float* __restrict__ g2,  const float* __restrict__ bb2,
    const float* __restrict__ Wb,  const float* __restrict__ bw,
    float* __restrict__ out, int N)
{
    const int tid = threadIdx.x;
    const int wid = tid >> 5;
    const int j   = tid >> 3;     // 0..15 neighbor
    const int l   = tid & 7;      // channel octet

    __shared__ __half s_WaH[8][72];    // [l][r*8+ch]
    __shared__ __half s_peH[8][40];    // [l][{W0,W1,W2,B2} x 8]
    __shared__ __half s_sbH[8][24];    // [l][{s1 x8, b1 x8}]
    __shared__ float  s_Wbt[8][12];    // Wb^T [lout][ch]
    __shared__ float  s_misc[64];      // 0:ba 8:s2 16:b2 24:bw 32:Wp1(9) 41:bp1 44:gp*binv 47:bp
    __shared__ float  s_wraw[16][12];
    __shared__ float  s_w[16][8];
    __shared__ float  s_part[4][72];

    const float bninv = rsqrtf(1.f + 1e-5f);

    // stage weights (once per block)
    for (int t = tid; t < 512; t += 128) {
        int c = t >> 3, ch = t & 7;
        s_WaH[c >> 3][(c & 7) * 8 + ch] = __float2half(__ldg(Wa + t));
    }
    if (tid < 64) {
        int ll = tid >> 3, m = tid & 7;
        int c = ll * 8 + m;
        s_peH[ll][0  + m] = __float2half(__ldg(Wp2 + c));
        s_peH[ll][8  + m] = __float2half(__ldg(Wp2 + 64 + c));
        s_peH[ll][16 + m] = __float2half(__ldg(Wp2 + 128 + c));
        s_peH[ll][24 + m] = __float2half(__ldg(bp2 + c));
        s_sbH[ll][m]      = __float2half(__ldg(g1 + c) * bninv);
        s_sbH[ll][8 + m]  = __float2half(__ldg(bb1 + c));
        s_Wbt[tid & 7][tid >> 3] = __ldg(Wb + tid);
    }
    if (tid < 8) {
        s_misc[tid]      = __ldg(ba + tid);
        s_misc[8 + tid]  = __ldg(g2 + tid) * bninv;
        s_misc[16 + tid] = __ldg(bb2 + tid);
        s_misc[24 + tid] = __ldg(bw + tid);
    }
    if (tid < 9)  s_misc[32 + tid] = __ldg(Wp1 + tid);
    if (tid < 3) {
        s_misc[41 + tid] = __ldg(bp1 + tid);
        s_misc[44 + tid] = __ldg(gp + tid) * bninv;
        s_misc[47 + tid] = __ldg(bpv + tid);
    }
    __syncthreads();

    // hoisted per-l constants (block-loop invariant)
    const float ba_l = s_misc[l];
    const float s2_l = s_misc[8 + l];
    const float b2_l = s_misc[16 + l];
    const float bw_l = s_misc[24 + l];
    float wbr[8];
    #pragma unroll
    for (int ch = 0; ch < 8; ch++) wbr[ch] = s_Wbt[l][ch];

    const int b2f = (l & 4);   // bit masks for shuffle patterns
    const int b1f = (l & 2);
    const int b0f = (l & 1);
    const int jb0 = (tid & 8);     // local_j bit0
    const int jb1 = (tid & 16);    // local_j bit1

    const int i0 = blockIdx.x * PTS;

    #pragma unroll 1
    for (int it = 0; it < PTS; it++) {
        const int i = i0 + it;
        const bool act = (i < N);            // uniform across block

        float val[8];

        if (act) {
            const int nj = __ldg(idx + i * NS + j);
            float4 pi4 = g_p4[i];            // broadcast, 1 wf
            float4 pn4 = g_p4[nj];           // gather,    1 LDG.128
            const float rx = pn4.x - pi4.x;
            const float ry = pn4.y - pi4.y;
            const float rz = pn4.z - pi4.z;
            float t3[3];
            #pragma unroll
            for (int o = 0; o < 3; o++) {
                float u = fmaf(rx, s_misc[32 + o],
                          fmaf(ry, s_misc[35 + o],
                          fmaf(rz, s_misc[38 + o], s_misc[41 + o])));
                t3[o] = fmaxf(fmaf(u, s_misc[44 + o], s_misc[47 + o]), 0.f);
            }
            __half2 t0h = __float2half2_rn(t3[0]);
            __half2 t1h = __float2half2_rn(t3[1]);
            __half2 t2h = __float2half2_rn(t3[2]);

            // one LDG.128 each: full fp16 8-channel chunk
            uint4 qr = *reinterpret_cast<const uint4*>(g_qh + (long long)i  * 64 + l * 8);
            uint4 kr = *reinterpret_cast<const uint4*>(g_kh + (long long)nj * 64 + l * 8);
            uint4 vr = *reinterpret_cast<const uint4*>(g_vh + (long long)nj * 64 + l * 8);

            const uint4* peL = reinterpret_cast<const uint4*>(&s_peH[l][0]);
            uint4 W0 = peL[0], W1 = peL[1], W2 = peL[2], B2 = peL[3];
            const uint4* sbL = reinterpret_cast<const uint4*>(&s_sbH[l][0]);
            uint4 S1 = sbL[0], B1 = sbL[1];

            float wv[8];
            const unsigned* qp = &qr.x;
            const unsigned* kp = &kr.x;
            const unsigned* vp = &vr.x;
            const unsigned* w0p = &W0.x; const unsigned* w1p = &W1.x;
            const unsigned* w2p = &W2.x; const unsigned* b2p = &B2.x;
            const unsigned* s1p = &S1.x; const unsigned* b1p = &B1.x;

            #pragma unroll
            for (int pp = 0; pp < 4; pp++) {
                __half2 pe2 = __hfma2(t0h, *(const __half2*)&w0p[pp],
                              __hfma2(t1h, *(const __half2*)&w1p[pp],
                              __hfma2(t2h, *(const __half2*)&w2p[pp],
                                      *(const __half2*)&b2p[pp])));
                float2 pef = __half22float2(pe2);
                float2 vf  = __half22float2(*(const __half2*)&vp[pp]);
                val[2*pp]   = vf.x + pef.x;
                val[2*pp+1] = vf.y + pef.y;
                __half2 d2 = __hsub2(*(const __half2*)&kp[pp], *(const __half2*)&qp[pp]);
                float2 df = __half22float2(d2);
                float2 s1f = __half22float2(*(const __half2*)&s1p[pp]);
                float2 b1f2 = __half22float2(*(const __half2*)&b1p[pp]);
                wv[2*pp]   = fmaxf(fmaf(df.x + pef.x, s1f.x, b1f2.x), 0.f);
                wv[2*pp+1] = fmaxf(fmaf(df.y + pef.y, s1f.y, b1f2.y), 0.f);
            }

            // y[ch] partials over this thread's 8 c's (HFMA2)
            __half2 wv2[4];
            #pragma unroll
            for (int pp = 0; pp < 4; pp++)
                wv2[pp] = __floats2half2_rn(wv[2*pp], wv[2*pp+1]);
            __half2 y2[4];
            y2[0] = y2[1] = y2[2] = y2[3] = __float2half2_rn(0.f);
            const uint4* waL = reinterpret_cast<const uint4*>(&s_WaH[l][0]);
            #pragma unroll
            for (int r = 0; r < 8; r++) {
                uint4 wa = waL[r];
                const unsigned* wap = &wa.x;
                __half2 wb2 = (r & 1) ? __high2half2(wv2[r >> 1])
                                      : __low2half2(wv2[r >> 1]);
                y2[0] = __hfma2(wb2, *(const __half2*)&wap[0], y2[0]);
                y2[1] = __hfma2(wb2, *(const __half2*)&wap[1], y2[1]);
                y2[2] = __hfma2(wb2, *(const __half2*)&wap[2], y2[2]);
                y2[3] = __hfma2(wb2, *(const __half2*)&wap[3], y2[3]);
            }
            float y[8];
            #pragma unroll
            for (int pp = 0; pp < 4; pp++) {
                float2 f = __half22float2(y2[pp]);
                y[2*pp] = f.x; y[2*pp+1] = f.y;
            }

            // ---- reduce-scatter over the 8-lane j-group: lane l ends with y_ch=l
            float k4v[4];
            #pragma unroll
            for (int m = 0; m < 4; m++) {
                float s = b2f ? y[m] : y[4 + m];
                float r = __shfl_xor_sync(0xffffffffu, s, 4);
                k4v[m] = (b2f ? y[4 + m] : y[m]) + r;
            }
            float k2v[2];
            #pragma unroll
            for (int m = 0; m < 2; m++) {
                float s = b1f ? k4v[m] : k4v[2 + m];
                float r = __shfl_xor_sync(0xffffffffu, s, 2);
                k2v[m] = (b1f ? k4v[2 + m] : k4v[m]) + r;
            }
            float yfin;
            {
                float s = b0f ? k2v[0] : k2v[1];
                float r = __shfl_xor_sync(0xffffffffu, s, 1);
                yfin = (b0f ? k2v[1] : k2v[0]) + r;
            }

            // BN2 + ReLU for channel l only
            float a = fmaxf(fmaf(yfin + ba_l, s2_l, b2_l), 0.f);

            // ---- allgather a[0..7] across the j-group (7 shuffles)
            float g[8];
            {
                float o1 = __shfl_xor_sync(0xffffffffu, a, 1);
                float p0 = b0f ? o1 : a;
                float p1 = b0f ? a  : o1;
                float q0 = __shfl_xor_sync(0xffffffffu, p0, 2);
                float q1 = __shfl_xor_sync(0xffffffffu, p1, 2);
                float h0, h1, h2, h3;
                if (b1f) { h0 = q0; h1 = q1; h2 = p0; h3 = p1; }
                else     { h0 = p0; h1 = p1; h2 = q0; h3 = q1; }
                float r0 = __shfl_xor_sync(0xffffffffu, h0, 4);
                float r1 = __shfl_xor_sync(0xffffffffu, h1, 4);
                float r2 = __shfl_xor_sync(0xffffffffu, h2, 4);
                float r3 = __shfl_xor_sync(0xffffffffu, h3, 4);
                if (b2f) { g[0]=r0; g[1]=r1; g[2]=r2; g[3]=r3; g[4]=h0; g[5]=h1; g[6]=h2; g[7]=h3; }
                else     { g[0]=h0; g[1]=h1; g[2]=h2; g[3]=h3; g[4]=r0; g[5]=r1; g[6]=r2; g[7]=r3; }
            }

            // Wb dot -> score channel l
            float sc = bw_l;
            #pragma unroll
            for (int ch = 0; ch < 8; ch++) sc = fmaf(g[ch], wbr[ch], sc);
            s_wraw[j][l] = sc;
        }
        __syncthreads();

        if (act && tid < 8) {
            float mx = -1e30f;
            #pragma unroll
            for (int jj = 0; jj < NS; jj++) mx = fmaxf(mx, s_wraw[jj][tid]);
            float sm = 0.f;
            #pragma unroll
            for (int jj = 0; jj < NS; jj++) sm += __expf(s_wraw[jj][tid] - mx);
            float inv = 1.f / sm;
            #pragma unroll
            for (int jj = 0; jj < NS; jj++)
                s_w[jj][tid] = __expf(s_wraw[jj][tid] - mx) * inv;
        }
        __syncthreads();

        if (act) {
            // weighted vals; reduce-scatter over the 4 in-warp neighbors
            float4 w4a = *(const float4*)&s_w[j][0];
            float4 w4b = *(const float4*)&s_w[j][4];
            float v[8];
            v[0] = val[0] * w4a.x; v[1] = val[1] * w4a.y;
            v[2] = val[2] * w4a.z; v[3] = val[3] * w4a.w;
            v[4] = val[4] * w4b.x; v[5] = val[5] * w4b.y;
            v[6] = val[6] * w4b.z; v[7] = val[7] * w4b.w;

            // round off=8: keep m in {0,1,4,5} if jb0==0 else {2,3,6,7}
            const int ks0[4] = {0, 1, 4, 5};
            const int ks1[4] = {2, 3, 6, 7};
            float kk[4];
            #pragma unroll
            for (int m = 0; m < 4; m++) {
                float s = jb0 ? v[ks0[m]] : v[ks1[m]];
                float r = __shfl_xor_sync(0xffffffffu, s, 8);
                kk[m] = (jb0 ? v[ks1[m]] : v[ks0[m]]) + r;
            }
            // round off=16: keep first two if jb1==0 else last two
            float fin0, fin1;
            {
                float s0 = jb1 ? kk[0] : kk[2];
                float s1 = jb1 ? kk[1] : kk[3];
                float r0 = __shfl_xor_sync(0xffffffffu, s0, 16);
                float r1 = __shfl_xor_sync(0xffffffffu, s1, 16);
                fin0 = (jb1 ? kk[2] : kk[0]) + r0;
                fin1 = (jb1 ? kk[3] : kk[1]) + r1;
            }
            // lane holds channels m = 2*local_j + {0,1}; store 8B
            const int lj = (tid >> 3) & 3;
            *(float2*)&s_part[wid][l * 8 + lj * 2] = make_float2(fin0, fin1);
        }
        __syncthreads();

        if (act && tid < 64) {
            float o = s_part[0][tid] + s_part[1][tid] + s_part[2][tid] + s_part[3][tid];
            out[(long long)i * 64 + tid] = o;
        }
    }
}

// ---------------------------------------------------------------------------
extern "C" void kernel_launch(void* const* d_in, const int* in_sizes, int n_in,
                              void* d_out, int out_size)
{
    const float* p   = (const float*)d_in[0];
    const float* x   = (const float*)d_in[1];
    const int*   idx = (const int*)  d_in[2];
    const float* Wq  = (const float*)d_in[3];
    const float* bq  = (const float*)d_in[4];
    const float* Wk  = (const float*)d_in[5];
    const float* bk  = (const float*)d_in[6];
    const float* Wv  = (const float*)d_in[7];
    const float* bv  = (const float*)d_in[8];
    const float* Wp1 = (const float*)d_in[9];
    const float* bp1 = (const float*)d_in[10];
    const float* gp  = (const float*)d_in[11];
    const float* bpv = (const float*)d_in[12];
    const float* Wp2 = (const float*)d_in[13];
    const float* bp2 = (const float*)d_in[14];
    const float* g1  = (const float*)d_in[15];
    const float* bb1 = (const float*)d_in[16];
    const float* Wa  = (const float*)d_in[17];
    const float* ba  = (const float*)d_in[18];
    const float* g2  = (const float*)d_in[19];
    const float* bb2 = (const float*)d_in[20];
    const float* Wb  = (const float*)d_in[21];
    const float* bw  = (const float*)d_in[22];
    float* out = (float*)d_out;

    int N = in_sizes[1] / C;
    if (N > MAXN) N = MAXN;

    pack_p4<<<(N + 255) / 256, 256>>>(p, N);

    dim3 gridA((N + 63) / 64, 3);
    qkv_gemm<<<gridA, 256>>>(x, Wq, bq, Wk, bk, Wv, bv, N);

    pt_attn<<<(N + PTS - 1) / PTS, 128>>>(p, idx, Wp1, bp1, gp, bpv, Wp2, bp2,
                                          g1, bb1, Wa, ba, g2, bb2, Wb, bw, out, N);
}

// round 11
// speedup vs baseline: 2.6347x; 1.1528x over previous
#include <cuda_runtime.h>
#include <cuda_fp16.h>
#include <math.h>

#define MAXN 100000
#define NS 16
#define C 64
#define PTS 8          // points per block (sequential) in pt_attn
#define QR 128         // rows per qkv block

// fp16 scratch for Q/K/V projections + packed positions
__device__ __half g_qh[MAXN * C];
__device__ __half g_kh[MAXN * C];
__device__ __half g_vh[MAXN * C];
__device__ float4 g_p4[MAXN];

__device__ __forceinline__ unsigned su32(const void* p) {
    return (unsigned)__cvta_generic_to_shared(p);
}

// ---------------------------------------------------------------------------
// Kernel 1: QKV projection on tensor cores (fp16 in, fp32 acc, fp16 out).
// Block: 256 threads = 8 warps; 128 rows. Also packs p -> g_p4.
// ---------------------------------------------------------------------------
__global__ void __launch_bounds__(256) qkv_mma(
    const float* __restrict__ x, const float* __restrict__ p,
    const float* __restrict__ Wq, const float* __restrict__ bq,
    const float* __restrict__ Wk, const float* __restrict__ bk,
    const float* __restrict__ Wv, const float* __restrict__ bv,
    int N)
{
    __shared__ __half xh[QR][72];     // stride 72 halves = 36 words: bank 4g+t
    __shared__ __half ws[64][72];

    const int tid = threadIdx.x;
    const int r0  = blockIdx.x * QR;

    // fold: pack p -> float4
    if (tid < QR) {
        int i = r0 + tid;
        if (i < N)
            g_p4[i] = make_float4(__ldg(p + i * 3 + 0), __ldg(p + i * 3 + 1),
                                  __ldg(p + i * 3 + 2), 0.f);
    }

    // stage x -> fp16 smem (2048 float4, 8 per thread)
    #pragma unroll
    for (int u = 0; u < 8; u++) {
        int i4  = tid + 256 * u;
        int row = i4 >> 4;
        int c4  = (i4 & 15) << 2;
        int gr  = r0 + row;
        float4 v = (gr < N) ? __ldg((const float4*)(x + (long long)gr * 64 + c4))
                            : make_float4(0.f, 0.f, 0.f, 0.f);
        *(__half2*)&xh[row][c4]     = __floats2half2_rn(v.x, v.y);
        *(__half2*)&xh[row][c4 + 2] = __floats2half2_rn(v.z, v.w);
    }
    __syncthreads();

    const int lane  = tid & 31;
    const int warp  = tid >> 5;
    const int group = lane >> 2;
    const int t4    = lane & 3;
    const int rbase = warp * 16;

    // A fragments: ldmatrix.x4 per k-chunk, reused across all 3 sets
    unsigned A[4][4];
    {
        int arow = rbase + (lane & 7) + ((lane >> 3) & 1) * 8;
        int acol = (lane >> 4) * 8;
        unsigned abase = su32(&xh[arow][acol]);
        #pragma unroll
        for (int kc = 0; kc < 4; kc++) {
            unsigned addr = abase + kc * 32;     // 16 halves = 32B per k-chunk
            asm volatile("ldmatrix.sync.aligned.m8n8.x4.shared.b16 {%0,%1,%2,%3}, [%4];"
                         : "=r"(A[kc][0]), "=r"(A[kc][1]), "=r"(A[kc][2]), "=r"(A[kc][3])
                         : "r"(addr));
        }
    }

    const unsigned bbase = su32(&ws[lane & 15][0]);

    #pragma unroll 1
    for (int s = 0; s < 3; s++) {
        const float* W = (s == 0) ? Wq : (s == 1) ? Wk : Wv;
        const float* b = (s == 0) ? bq : (s == 1) ? bk : bv;
        __half* outp   = (s == 0) ? g_qh : (s == 1) ? g_kh : g_vh;

        // stage W -> fp16 smem (coalesced)
        #pragma unroll
        for (int u = 0; u < 4; u++) {
            int i4 = tid + 256 * u;
            int k  = i4 >> 4;
            int n4 = (i4 & 15) << 2;
            float4 wv = __ldg((const float4*)(W + k * 64 + n4));
            *(__half2*)&ws[k][n4]     = __floats2half2_rn(wv.x, wv.y);
            *(__half2*)&ws[k][n4 + 2] = __floats2half2_rn(wv.z, wv.w);
        }
        __syncthreads();

        #pragma unroll
        for (int nt = 0; nt < 8; nt++) {
            const int n0 = nt * 8;
            float bx = __ldg(b + n0 + t4 * 2);
            float by = __ldg(b + n0 + t4 * 2 + 1);
            float c0 = bx, c1 = by, c2 = bx, c3 = by;
            #pragma unroll
            for (int kc = 0; kc < 4; kc++) {
                unsigned b0, b1;
                unsigned addr = bbase + kc * 16 * 144 + n0 * 2;   // row kc*16+(lane&15), col n0
                asm volatile("ldmatrix.sync.aligned.m8n8.x2.trans.shared.b16 {%0,%1}, [%2];"
                             : "=r"(b0), "=r"(b1) : "r"(addr));
                asm volatile(
                    "mma.sync.aligned.m16n8k16.row.col.f32.f16.f16.f32 "
                    "{%0,%1,%2,%3}, {%4,%5,%6,%7}, {%8,%9}, {%0,%1,%2,%3};"
                    : "+f"(c0), "+f"(c1), "+f"(c2), "+f"(c3)
                    : "r"(A[kc][0]), "r"(A[kc][1]), "r"(A[kc][2]), "r"(A[kc][3]),
                      "r"(b0), "r"(b1));
            }
            int gr0 = r0 + rbase + group;
            int gr1 = gr0 + 8;
            if (gr0 < N)
                *(__half2*)(outp + (long long)gr0 * 64 + n0 + t4 * 2) = __floats2half2_rn(c0, c1);
            if (gr1 < N)
                *(__half2*)(outp + (long long)gr1 * 64 + n0 + t4 * 2) = __floats2half2_rn(c2, c3);
        }
        __syncthreads();
    }
}

// ---------------------------------------------------------------------------
// Kernel 2: per-point attention (unchanged from R10 best).
// Thread (j = tid>>3, l = tid&7): neighbor j, channels c = l*8 .. l*8+7.
// ---------------------------------------------------------------------------
__global__ void __launch_bounds__(128) pt_attn(
    const int*   __restrict__ idx,
    const float* __restrict__ Wp1, const float* __restrict__ bp1,
    const float* __restrict__ gp,  const float* __restrict__ bpv,
    const float* __restrict__ Wp2, const float* __restrict__ bp2,
    const float* __restrict__ g1,  const float* __restrict__ bb1,
    const float* __restrict__ Wa,  const float* __restrict__ ba,
    const float* __restrict__ g2,  const float* __restrict__ bb2,
    const float* __restrict__ Wb,  const float* __restrict__ bw,
    float* __restrict__ out, int N)
{
    const int tid = threadIdx.x;
    const int wid = tid >> 5;
    const int j   = tid >> 3;
    const int l   = tid & 7;

    __shared__ __half s_WaH[8][72];
    __shared__ __half s_peH[8][40];
    __shared__ __half s_sbH[8][24];
    __shared__ float  s_Wbt[8][12];
    __shared__ float  s_misc[64];
    __shared__ float  s_wraw[16][12];
    __shared__ float  s_w[16][8];
    __shared__ float  s_part[4][72];

    const float bninv = rsqrtf(1.f + 1e-5f);

    for (int t = tid; t < 512; t += 128) {
        int c = t >> 3, ch = t & 7;
        s_WaH[c >> 3][(c & 7) * 8 + ch] = __float2half(__ldg(Wa + t));
    }
    if (tid < 64) {
        int ll = tid >> 3, m = tid & 7;
        int c = ll * 8 + m;
        s_peH[ll][0  + m] = __float2half(__ldg(Wp2 + c));
        s_peH[ll][8  + m] = __float2half(__ldg(Wp2 + 64 + c));
        s_peH[ll][16 + m] = __float2half(__ldg(Wp2 + 128 + c));
        s_peH[ll][24 + m] = __float2half(__ldg(bp2 + c));
        s_sbH[ll][m]      = __float2half(__ldg(g1 + c) * bninv);
        s_sbH[ll][8 + m]  = __float2half(__ldg(bb1 + c));
        s_Wbt[tid & 7][tid >> 3] = __ldg(Wb + tid);
    }
    if (tid < 8) {
        s_misc[tid]      = __ldg(ba + tid);
        s_misc[8 + tid]  = __ldg(g2 + tid) * bninv;
        s_misc[16 + tid] = __ldg(bb2 + tid);
        s_misc[24 + tid] = __ldg(bw + tid);
    }
    if (tid < 9)  s_misc[32 + tid] = __ldg(Wp1 + tid);
    if (tid < 3) {
        s_misc[41 + tid] = __ldg(bp1 + tid);
        s_misc[44 + tid] = __ldg(gp + tid) * bninv;
        s_misc[47 + tid] = __ldg(bpv + tid);
    }
    __syncthreads();

    const float ba_l = s_misc[l];
    const float s2_l = s_misc[8 + l];
    const float b2_l = s_misc[16 + l];
    const float bw_l = s_misc[24 + l];
    float wbr[8];
    #pragma unroll
    for (int ch = 0; ch < 8; ch++) wbr[ch] = s_Wbt[l][ch];

    const int b2f = (l & 4);
    const int b1f = (l & 2);
    const int b0f = (l & 1);
    const int jb0 = (tid & 8);
    const int jb1 = (tid & 16);

    const int i0 = blockIdx.x * PTS;

    #pragma unroll 1
    for (int it = 0; it < PTS; it++) {
        const int i = i0 + it;
        const bool act = (i < N);

        float val[8];

        if (act) {
            const int nj = __ldg(idx + i * NS + j);
            float4 pi4 = g_p4[i];
            float4 pn4 = g_p4[nj];
            const float rx = pn4.x - pi4.x;
            const float ry = pn4.y - pi4.y;
            const float rz = pn4.z - pi4.z;
            float t3[3];
            #pragma unroll
            for (int o = 0; o < 3; o++) {
                float u = fmaf(rx, s_misc[32 + o],
                          fmaf(ry, s_misc[35 + o],
                          fmaf(rz, s_misc[38 + o], s_misc[41 + o])));
                t3[o] = fmaxf(fmaf(u, s_misc[44 + o], s_misc[47 + o]), 0.f);
            }
            __half2 t0h = __float2half2_rn(t3[0]);
            __half2 t1h = __float2half2_rn(t3[1]);
            __half2 t2h = __float2half2_rn(t3[2]);

            uint4 qr = *reinterpret_cast<const uint4*>(g_qh + (long long)i  * 64 + l * 8);
            uint4 kr = *reinterpret_cast<const uint4*>(g_kh + (long long)nj * 64 + l * 8);
            uint4 vr = *reinterpret_cast<const uint4*>(g_vh + (long long)nj * 64 + l * 8);

            const uint4* peL = reinterpret_cast<const uint4*>(&s_peH[l][0]);
            uint4 W0 = peL[0], W1 = peL[1], W2 = peL[2], B2 = peL[3];
            const uint4* sbL = reinterpret_cast<const uint4*>(&s_sbH[l][0]);
            uint4 S1 = sbL[0], B1 = sbL[1];

            float wv[8];
            const unsigned* qp = &qr.x;
            const unsigned* kp = &kr.x;
            const unsigned* vp = &vr.x;
            const unsigned* w0p = &W0.x; const unsigned* w1p = &W1.x;
            const unsigned* w2p = &W2.x; const unsigned* b2p = &B2.x;
            const unsigned* s1p = &S1.x; const unsigned* b1p = &B1.x;

            #pragma unroll
            for (int pp = 0; pp < 4; pp++) {
                __half2 pe2 = __hfma2(t0h, *(const __half2*)&w0p[pp],
                              __hfma2(t1h, *(const __half2*)&w1p[pp],
                              __hfma2(t2h, *(const __half2*)&w2p[pp],
                                      *(const __half2*)&b2p[pp])));
                float2 pef = __half22float2(pe2);
                float2 vf  = __half22float2(*(const __half2*)&vp[pp]);
                val[2*pp]   = vf.x + pef.x;
                val[2*pp+1] = vf.y + pef.y;
                __half2 d2 = __hsub2(*(const __half2*)&kp[pp], *(const __half2*)&qp[pp]);
                float2 df = __half22float2(d2);
                float2 s1f = __half22float2(*(const __half2*)&s1p[pp]);
                float2 b1f2 = __half22float2(*(const __half2*)&b1p[pp]);
                wv[2*pp]   = fmaxf(fmaf(df.x + pef.x, s1f.x, b1f2.x), 0.f);
                wv[2*pp+1] = fmaxf(fmaf(df.y + pef.y, s1f.y, b1f2.y), 0.f);
            }

            __half2 wv2[4];
            #pragma unroll
            for (int pp = 0; pp < 4; pp++)
                wv2[pp] = __floats2half2_rn(wv[2*pp], wv[2*pp+1]);
            __half2 y2[4];
            y2[0] = y2[1] = y2[2] = y2[3] = __float2half2_rn(0.f);
            const uint4* waL = reinterpret_cast<const uint4*>(&s_WaH[l][0]);
            #pragma unroll
            for (int r = 0; r < 8; r++) {
                uint4 wa = waL[r];
                const unsigned* wap = &wa.x;
                __half2 wb2 = (r & 1) ? __high2half2(wv2[r >> 1])
                                      : __low2half2(wv2[r >> 1]);
                y2[0] = __hfma2(wb2, *(const __half2*)&wap[0], y2[0]);
                y2[1] = __hfma2(wb2, *(const __half2*)&wap[1], y2[1]);
                y2[2] = __hfma2(wb2, *(const __half2*)&wap[2], y2[2]);
                y2[3] = __hfma2(wb2, *(const __half2*)&wap[3], y2[3]);
            }
            float y[8];
            #pragma unroll
            for (int pp = 0; pp < 4; pp++) {
                float2 f = __half22float2(y2[pp]);
                y[2*pp] = f.x; y[2*pp+1] = f.y;
            }

            // reduce-scatter over 8-lane j-group
            float k4v[4];
            #pragma unroll
            for (int m = 0; m < 4; m++) {
                float s = b2f ? y[m] : y[4 + m];
                float r = __shfl_xor_sync(0xffffffffu, s, 4);
                k4v[m] = (b2f ? y[4 + m] : y[m]) + r;
            }
            float k2v[2];
            #pragma unroll
            for (int m = 0; m < 2; m++) {
                float s = b1f ? k4v[m] : k4v[2 + m];
                float r = __shfl_xor_sync(0xffffffffu, s, 2);
                k2v[m] = (b1f ? k4v[2 + m] : k4v[m]) + r;
            }
            float yfin;
            {
                float s = b0f ? k2v[0] : k2v[1];
                float r = __shfl_xor_sync(0xffffffffu, s, 1);
                yfin = (b0f ? k2v[1] : k2v[0]) + r;
            }

            float a = fmaxf(fmaf(yfin + ba_l, s2_l, b2_l), 0.f);

            // allgather a[0..7]
            float g[8];
            {
                float o1 = __shfl_xor_sync(0xffffffffu, a, 1);
                float p0 = b0f ? o1 : a;
                float p1 = b0f ? a  : o1;
                float q0 = __shfl_xor_sync(0xffffffffu, p0, 2);
                float q1 = __shfl_xor_sync(0xffffffffu, p1, 2);
                float h0, h1, h2, h3;
                if (b1f) { h0 = q0; h1 = q1; h2 = p0; h3 = p1; }
                else     { h0 = p0; h1 = p1; h2 = q0; h3 = q1; }
                float r0 = __shfl_xor_sync(0xffffffffu, h0, 4);
                float r1 = __shfl_xor_sync(0xffffffffu, h1, 4);
                float r2 = __shfl_xor_sync(0xffffffffu, h2, 4);
                float r3 = __shfl_xor_sync(0xffffffffu, h3, 4);
                if (b2f) { g[0]=r0; g[1]=r1; g[2]=r2; g[3]=r3; g[4]=h0; g[5]=h1; g[6]=h2; g[7]=h3; }
                else     { g[0]=h0; g[1]=h1; g[2]=h2; g[3]=h3; g[4]=r0; g[5]=r1; g[6]=r2; g[7]=r3; }
            }

            float sc = bw_l;
            #pragma unroll
            for (int ch = 0; ch < 8; ch++) sc = fmaf(g[ch], wbr[ch], sc);
            s_wraw[j][l] = sc;
        }
        __syncthreads();

        if (act && tid < 8) {
            float mx = -1e30f;
            #pragma unroll
            for (int jj = 0; jj < NS; jj++) mx = fmaxf(mx, s_wraw[jj][tid]);
            float sm = 0.f;
            #pragma unroll
            for (int jj = 0; jj < NS; jj++) sm += __expf(s_wraw[jj][tid] - mx);
            float inv = 1.f / sm;
            #pragma unroll
            for (int jj = 0; jj < NS; jj++)
                s_w[jj][tid] = __expf(s_wraw[jj][tid] - mx) * inv;
        }
        __syncthreads();

        if (act) {
            float4 w4a = *(const float4*)&s_w[j][0];
            float4 w4b = *(const float4*)&s_w[j][4];
            float v[8];
            v[0] = val[0] * w4a.x; v[1] = val[1] * w4a.y;
            v[2] = val[2] * w4a.z; v[3] = val[3] * w4a.w;
            v[4] = val[4] * w4b.x; v[5] = val[5] * w4b.y;
            v[6] = val[6] * w4b.z; v[7] = val[7] * w4b.w;

            const int ks0[4] = {0, 1, 4, 5};
            const int ks1[4] = {2, 3, 6, 7};
            float kk[4];
            #pragma unroll
            for (int m = 0; m < 4; m++) {
                float s = jb0 ? v[ks0[m]] : v[ks1[m]];
                float r = __shfl_xor_sync(0xffffffffu, s, 8);
                kk[m] = (jb0 ? v[ks1[m]] : v[ks0[m]]) + r;
            }
            float fin0, fin1;
            {
                float s0 = jb1 ? kk[0] : kk[2];
                float s1 = jb1 ? kk[1] : kk[3];
                float r0 = __shfl_xor_sync(0xffffffffu, s0, 16);
                float r1 = __shfl_xor_sync(0xffffffffu, s1, 16);
                fin0 = (jb1 ? kk[2] : kk[0]) + r0;
                fin1 = (jb1 ? kk[3] : kk[1]) + r1;
            }
            const int lj = (tid >> 3) & 3;
            *(float2*)&s_part[wid][l * 8 + lj * 2] = make_float2(fin0, fin1);
        }
        __syncthreads();

        if (act && tid < 64) {
            float o = s_part[0][tid] + s_part[1][tid] + s_part[2][tid] + s_part[3][tid];
            out[(long long)i * 64 + tid] = o;
        }
    }
}

// ---------------------------------------------------------------------------
extern "C" void kernel_launch(void* const* d_in, const int* in_sizes, int n_in,
                              void* d_out, int out_size)
{
    const float* p   = (const float*)d_in[0];
    const float* x   = (const float*)d_in[1];
    const int*   idx = (const int*)  d_in[2];
    const float* Wq  = (const float*)d_in[3];
    const float* bq  = (const float*)d_in[4];
    const float* Wk  = (const float*)d_in[5];
    const float* bk  = (const float*)d_in[6];
    const float* Wv  = (const float*)d_in[7];
    const float* bv  = (const float*)d_in[8];
    const float* Wp1 = (const float*)d_in[9];
    const float* bp1 = (const float*)d_in[10];
    const float* gp  = (const float*)d_in[11];
    const float* bpv = (const float*)d_in[12];
    const float* Wp2 = (const float*)d_in[13];
    const float* bp2 = (const float*)d_in[14];
    const float* g1  = (const float*)d_in[15];
    const float* bb1 = (const float*)d_in[16];
    const float* Wa  = (const float*)d_in[17];
    const float* ba  = (const float*)d_in[18];
    const float* g2  = (const float*)d_in[19];
    const float* bb2 = (const float*)d_in[20];
    const float* Wb  = (const float*)d_in[21];
    const float* bw  = (const float*)d_in[22];
    float* out = (float*)d_out;

    int N = in_sizes[1] / C;
    if (N > MAXN) N = MAXN;

    qkv_mma<<<(N + QR - 1) / QR, 256>>>(x, p, Wq, bq, Wk, bk, Wv, bv, N);

    pt_attn<<<(N + PTS - 1) / PTS, 128>>>(idx, Wp1, bp1, gp, bpv, Wp2, bp2,
                                          g1, bb1, Wa, ba, g2, bb2, Wb, bw, out, N);
}

// round 15
// speedup vs baseline: 2.7492x; 1.0435x over previous
#include <cuda_runtime.h>
#include <cuda_fp16.h>
#include <math.h>

#define MAXN 100000
#define NS 16
#define C 64
#define PTS 16         // points per block (sequential) in pt_attn
#define QR 128         // rows per qkv block

// fp16 scratch for Q/K/V projections + packed positions
__device__ __half g_qh[MAXN * C];
__device__ __half g_kh[MAXN * C];
__device__ __half g_vh[MAXN * C];
__device__ float4 g_p4[MAXN];

__device__ __forceinline__ unsigned su32(const void* p) {
    return (unsigned)__cvta_generic_to_shared(p);
}

// ---------------------------------------------------------------------------
// Kernel 1: QKV projection on tensor cores (fp16 in, fp32 acc, fp16 out).
// Block: 256 threads = 8 warps; 128 rows. Also packs p -> g_p4.
// ---------------------------------------------------------------------------
__global__ void __launch_bounds__(256) qkv_mma(
    const float* __restrict__ x, const float* __restrict__ p,
    const float* __restrict__ Wq, const float* __restrict__ bq,
    const float* __restrict__ Wk, const float* __restrict__ bk,
    const float* __restrict__ Wv, const float* __restrict__ bv,
    int N)
{
    __shared__ __half xh[QR][72];     // stride 72 halves = 36 words: bank 4g+t
    __shared__ __half ws[64][72];

    const int tid = threadIdx.x;
    const int r0  = blockIdx.x * QR;

    // fold: pack p -> float4
    if (tid < QR) {
        int i = r0 + tid;
        if (i < N)
            g_p4[i] = make_float4(__ldg(p + i * 3 + 0), __ldg(p + i * 3 + 1),
                                  __ldg(p + i * 3 + 2), 0.f);
    }

    // stage x -> fp16 smem (2048 float4, 8 per thread)
    #pragma unroll
    for (int u = 0; u < 8; u++) {
        int i4  = tid + 256 * u;
        int row = i4 >> 4;
        int c4  = (i4 & 15) << 2;
        int gr  = r0 + row;
        float4 v = (gr < N) ? __ldg((const float4*)(x + (long long)gr * 64 + c4))
                            : make_float4(0.f, 0.f, 0.f, 0.f);
        *(__half2*)&xh[row][c4]     = __floats2half2_rn(v.x, v.y);
        *(__half2*)&xh[row][c4 + 2] = __floats2half2_rn(v.z, v.w);
    }
    __syncthreads();

    const int lane  = tid & 31;
    const int warp  = tid >> 5;
    const int group = lane >> 2;
    const int t4    = lane & 3;
    const int rbase = warp * 16;

    // A fragments: ldmatrix.x4 per k-chunk, reused across all 3 sets
    unsigned A[4][4];
    {
        int arow = rbase + (lane & 7) + ((lane >> 3) & 1) * 8;
        int acol = (lane >> 4) * 8;
        unsigned abase = su32(&xh[arow][acol]);
        #pragma unroll
        for (int kc = 0; kc < 4; kc++) {
            unsigned addr = abase + kc * 32;     // 16 halves = 32B per k-chunk
            asm volatile("ldmatrix.sync.aligned.m8n8.x4.shared.b16 {%0,%1,%2,%3}, [%4];"
                         : "=r"(A[kc][0]), "=r"(A[kc][1]), "=r"(A[kc][2]), "=r"(A[kc][3])
                         : "r"(addr));
        }
    }

    const unsigned bbase = su32(&ws[lane & 15][0]);

    #pragma unroll 1
    for (int s = 0; s < 3; s++) {
        const float* W = (s == 0) ? Wq : (s == 1) ? Wk : Wv;
        const float* b = (s == 0) ? bq : (s == 1) ? bk : bv;
        __half* outp   = (s == 0) ? g_qh : (s == 1) ? g_kh : g_vh;

        // stage W -> fp16 smem (coalesced)
        #pragma unroll
        for (int u = 0; u < 4; u++) {
            int i4 = tid + 256 * u;
            int k  = i4 >> 4;
            int n4 = (i4 & 15) << 2;
            float4 wv = __ldg((const float4*)(W + k * 64 + n4));
            *(__half2*)&ws[k][n4]     = __floats2half2_rn(wv.x, wv.y);
            *(__half2*)&ws[k][n4 + 2] = __floats2half2_rn(wv.z, wv.w);
        }
        __syncthreads();

        #pragma unroll
        for (int nt = 0; nt < 8; nt++) {
            const int n0 = nt * 8;
            float bx = __ldg(b + n0 + t4 * 2);
            float by = __ldg(b + n0 + t4 * 2 + 1);
            float c0 = bx, c1 = by, c2 = bx, c3 = by;
            #pragma unroll
            for (int kc = 0; kc < 4; kc++) {
                unsigned b0, b1;
                unsigned addr = bbase + kc * 16 * 144 + n0 * 2;   // row kc*16+(lane&15), col n0
                asm volatile("ldmatrix.sync.aligned.m8n8.x2.trans.shared.b16 {%0,%1}, [%2];"
                             : "=r"(b0), "=r"(b1) : "r"(addr));
                asm volatile(
                    "mma.sync.aligned.m16n8k16.row.col.f32.f16.f16.f32 "
                    "{%0,%1,%2,%3}, {%4,%5,%6,%7}, {%8,%9}, {%0,%1,%2,%3};"
                    : "+f"(c0), "+f"(c1), "+f"(c2), "+f"(c3)
                    : "r"(A[kc][0]), "r"(A[kc][1]), "r"(A[kc][2]), "r"(A[kc][3]),
                      "r"(b0), "r"(b1));
            }
            int gr0 = r0 + rbase + group;
            int gr1 = gr0 + 8;
            if (gr0 < N)
                *(__half2*)(outp + (long long)gr0 * 64 + n0 + t4 * 2) = __floats2half2_rn(c0, c1);
            if (gr1 < N)
                *(__half2*)(outp + (long long)gr1 * 64 + n0 + t4 * 2) = __floats2half2_rn(c2, c3);
        }
        __syncthreads();
    }
}

// ---------------------------------------------------------------------------
// Kernel 2: per-point attention. 128 threads, PTS points sequential,
// forced <=64 regs for 8 blocks/SM occupancy.
// Thread (j = tid>>3, l = tid&7): neighbor j, channels c = l*8 .. l*8+7.
// ---------------------------------------------------------------------------
__global__ void __launch_bounds__(128, 8) pt_attn(
    const int*   __restrict__ idx,
    const float* __restrict__ Wp1, const float* __restrict__ bp1,
    const float* __restrict__ gp,  const float* __restrict__ bpv,
    const float* __restrict__ Wp2, const float* __restrict__ bp2,
    const float* __restrict__ g1,  const float* __restrict__ bb1,
    const float* __restrict__ Wa,  const float* __restrict__ ba,
    const float* __restrict__ g2,  const float* __restrict__ bb2,
    const float* __restrict__ Wb,  const float* __restrict__ bw,
    float* __restrict__ out, int N)
{
    const int tid = threadIdx.x;
    const int wid = tid >> 5;
    const int j   = tid >> 3;
    const int l   = tid & 7;

    __shared__ __half s_WaH[8][72];
    __shared__ __half s_peH[8][40];
    __shared__ __half s_sbH[8][24];
    __shared__ float  s_Wbt[8][12];
    __shared__ float  s_misc[64];
    __shared__ float  s_wraw[16][12];
    __shared__ float  s_w[16][8];
    __shared__ float  s_part[4][72];

    const float bninv = rsqrtf(1.f + 1e-5f);

    for (int t = tid; t < 512; t += 128) {
        int c = t >> 3, ch = t & 7;
        s_WaH[c >> 3][(c & 7) * 8 + ch] = __float2half(__ldg(Wa + t));
    }
    if (tid < 64) {
        int ll = tid >> 3, m = tid & 7;
        int c = ll * 8 + m;
        s_peH[ll][0  + m] = __float2half(__ldg(Wp2 + c));
        s_peH[ll][8  + m] = __float2half(__ldg(Wp2 + 64 + c));
        s_peH[ll][16 + m] = __float2half(__ldg(Wp2 + 128 + c));
        s_peH[ll][24 + m] = __float2half(__ldg(bp2 + c));
        s_sbH[ll][m]      = __float2half(__ldg(g1 + c) * bninv);
        s_sbH[ll][8 + m]  = __float2half(__ldg(bb1 + c));
        s_Wbt[tid & 7][tid >> 3] = __ldg(Wb + tid);
    }
    if (tid < 8) {
        s_misc[tid]      = __ldg(ba + tid);
        s_misc[8 + tid]  = __ldg(g2 + tid) * bninv;
        s_misc[16 + tid] = __ldg(bb2 + tid);
        s_misc[24 + tid] = __ldg(bw + tid);
    }
    if (tid < 9)  s_misc[32 + tid] = __ldg(Wp1 + tid);
    if (tid < 3) {
        s_misc[41 + tid] = __ldg(bp1 + tid);
        s_misc[44 + tid] = __ldg(gp + tid) * bninv;
        s_misc[47 + tid] = __ldg(bpv + tid);
    }
    __syncthreads();

    const int b2f = (l & 4);
    const int b1f = (l & 2);
    const int b0f = (l & 1);
    const int jb0 = (tid & 8);
    const int jb1 = (tid & 16);

    const int i0 = blockIdx.x * PTS;

    #pragma unroll 1
    for (int it = 0; it < PTS; it++) {
        const int i = i0 + it;
        const bool act = (i < N);

        float val[8];

        if (act) {
            const int nj = __ldg(idx + i * NS + j);
            float4 pi4 = g_p4[i];
            float4 pn4 = g_p4[nj];
            const float rx = pn4.x - pi4.x;
            const float ry = pn4.y - pi4.y;
            const float rz = pn4.z - pi4.z;
            float t3[3];
            #pragma unroll
            for (int o = 0; o < 3; o++) {
                float u = fmaf(rx, s_misc[32 + o],
                          fmaf(ry, s_misc[35 + o],
                          fmaf(rz, s_misc[38 + o], s_misc[41 + o])));
                t3[o] = fmaxf(fmaf(u, s_misc[44 + o], s_misc[47 + o]), 0.f);
            }
            __half2 t0h = __float2half2_rn(t3[0]);
            __half2 t1h = __float2half2_rn(t3[1]);
            __half2 t2h = __float2half2_rn(t3[2]);

            uint4 qr = *reinterpret_cast<const uint4*>(g_qh + (long long)i  * 64 + l * 8);
            uint4 kr = *reinterpret_cast<const uint4*>(g_kh + (long long)nj * 64 + l * 8);
            uint4 vr = *reinterpret_cast<const uint4*>(g_vh + (long long)nj * 64 + l * 8);

            const uint4* peL = reinterpret_cast<const uint4*>(&s_peH[l][0]);
            uint4 W0 = peL[0], W1 = peL[1], W2 = peL[2], B2 = peL[3];
            const uint4* sbL = reinterpret_cast<const uint4*>(&s_sbH[l][0]);
            uint4 S1 = sbL[0], B1 = sbL[1];

            float wv[8];
            const unsigned* qp = &qr.x;
            const unsigned* kp = &kr.x;
            const unsigned* vp = &vr.x;
            const unsigned* w0p = &W0.x; const unsigned* w1p = &W1.x;
            const unsigned* w2p = &W2.x; const unsigned* b2p = &B2.x;
            const unsigned* s1p = &S1.x; const unsigned* b1p = &B1.x;

            #pragma unroll
            for (int pp = 0; pp < 4; pp++) {
                __half2 pe2 = __hfma2(t0h, *(const __half2*)&w0p[pp],
                              __hfma2(t1h, *(const __half2*)&w1p[pp],
                              __hfma2(t2h, *(const __half2*)&w2p[pp],
                                      *(const __half2*)&b2p[pp])));
                float2 pef = __half22float2(pe2);
                float2 vf  = __half22float2(*(const __half2*)&vp[pp]);
                val[2*pp]   = vf.x + pef.x;
                val[2*pp+1] = vf.y + pef.y;
                __half2 d2 = __hsub2(*(const __half2*)&kp[pp], *(const __half2*)&qp[pp]);
                float2 df = __half22float2(d2);
                float2 s1f = __half22float2(*(const __half2*)&s1p[pp]);
                float2 b1f2 = __half22float2(*(const __half2*)&b1p[pp]);
                wv[2*pp]   = fmaxf(fmaf(df.x + pef.x, s1f.x, b1f2.x), 0.f);
                wv[2*pp+1] = fmaxf(fmaf(df.y + pef.y, s1f.y, b1f2.y), 0.f);
            }

            __half2 wv2[4];
            #pragma unroll
            for (int pp = 0; pp < 4; pp++)
                wv2[pp] = __floats2half2_rn(wv[2*pp], wv[2*pp+1]);
            __half2 y2[4];
            y2[0] = y2[1] = y2[2] = y2[3] = __float2half2_rn(0.f);
            const uint4* waL = reinterpret_cast<const uint4*>(&s_WaH[l][0]);
            #pragma unroll
            for (int r = 0; r < 8; r++) {
                uint4 wa = waL[r];
                const unsigned* wap = &wa.x;
                __half2 wb2 = (r & 1) ? __high2half2(wv2[r >> 1])
                                      : __low2half2(wv2[r >> 1]);
                y2[0] = __hfma2(wb2, *(const __half2*)&wap[0], y2[0]);
                y2[1] = __hfma2(wb2, *(const __half2*)&wap[1], y2[1]);
                y2[2] = __hfma2(wb2, *(const __half2*)&wap[2], y2[2]);
                y2[3] = __hfma2(wb2, *(const __half2*)&wap[3], y2[3]);
            }
            float y[8];
            #pragma unroll
            for (int pp = 0; pp < 4; pp++) {
                float2 f = __half22float2(y2[pp]);
                y[2*pp] = f.x; y[2*pp+1] = f.y;
            }

            // reduce-scatter over 8-lane j-group: lane l ends with y_ch=l
            float k4v[4];
            #pragma unroll
            for (int m = 0; m < 4; m++) {
                float s = b2f ? y[m] : y[4 + m];
                float r = __shfl_xor_sync(0xffffffffu, s, 4);
                k4v[m] = (b2f ? y[4 + m] : y[m]) + r;
            }
            float k2v[2];
            #pragma unroll
            for (int m = 0; m < 2; m++) {
                float s = b1f ? k4v[m] : k4v[2 + m];
                float r = __shfl_xor_sync(0xffffffffu, s, 2);
                k2v[m] = (b1f ? k4v[2 + m] : k4v[m]) + r;
            }
            float yfin;
            {
                float s = b0f ? k2v[0] : k2v[1];
                float r = __shfl_xor_sync(0xffffffffu, s, 1);
                yfin = (b0f ? k2v[1] : k2v[0]) + r;
            }

            float a = fmaxf(fmaf(yfin + s_misc[l], s_misc[8 + l], s_misc[16 + l]), 0.f);

            // allgather a[0..7]
            float g[8];
            {
                float o1 = __shfl_xor_sync(0xffffffffu, a, 1);
                float p0 = b0f ? o1 : a;
                float p1 = b0f ? a  : o1;
                float q0 = __shfl_xor_sync(0xffffffffu, p0, 2);
                float q1 = __shfl_xor_sync(0xffffffffu, p1, 2);
                float h0, h1, h2, h3;
                if (b1f) { h0 = q0; h1 = q1; h2 = p0; h3 = p1; }
                else     { h0 = p0; h1 = p1; h2 = q0; h3 = q1; }
                float r0 = __shfl_xor_sync(0xffffffffu, h0, 4);
                float r1 = __shfl_xor_sync(0xffffffffu, h1, 4);
                float r2 = __shfl_xor_sync(0xffffffffu, h2, 4);
                float r3 = __shfl_xor_sync(0xffffffffu, h3, 4);
                if (b2f) { g[0]=r0; g[1]=r1; g[2]=r2; g[3]=r3; g[4]=h0; g[5]=h1; g[6]=h2; g[7]=h3; }
                else     { g[0]=h0; g[1]=h1; g[2]=h2; g[3]=h3; g[4]=r0; g[5]=r1; g[6]=r2; g[7]=r3; }
            }

            float sc = s_misc[24 + l];
            #pragma unroll
            for (int ch = 0; ch < 8; ch++) sc = fmaf(g[ch], s_Wbt[l][ch], sc);
            s_wraw[j][l] = sc;
        }
        __syncthreads();

        if (act && tid < 8) {
            float mx = -1e30f;
            #pragma unroll
            for (int jj = 0; jj < NS; jj++) mx = fmaxf(mx, s_wraw[jj][tid]);
            float sm = 0.f;
            #pragma unroll
            for (int jj = 0; jj < NS; jj++) sm += __expf(s_wraw[jj][tid] - mx);
            float inv = 1.f / sm;
            #pragma unroll
            for (int jj = 0; jj < NS; jj++)
                s_w[jj][tid] = __expf(s_wraw[jj][tid] - mx) * inv;
        }
        __syncthreads();

        if (act) {
            float4 w4a = *(const float4*)&s_w[j][0];
            float4 w4b = *(const float4*)&s_w[j][4];
            float v[8];
            v[0] = val[0] * w4a.x; v[1] = val[1] * w4a.y;
            v[2] = val[2] * w4a.z; v[3] = val[3] * w4a.w;
            v[4] = val[4] * w4b.x; v[5] = val[5] * w4b.y;
            v[6] = val[6] * w4b.z; v[7] = val[7] * w4b.w;

            const int ks0[4] = {0, 1, 4, 5};
            const int ks1[4] = {2, 3, 6, 7};
            float kk[4];
            #pragma unroll
            for (int m = 0; m < 4; m++) {
                float s = jb0 ? v[ks0[m]] : v[ks1[m]];
                float r = __shfl_xor_sync(0xffffffffu, s, 8);
                kk[m] = (jb0 ? v[ks1[m]] : v[ks0[m]]) + r;
            }
            float fin0, fin1;
            {
                float s0 = jb1 ? kk[0] : kk[2];
                float s1 = jb1 ? kk[1] : kk[3];
                float r0 = __shfl_xor_sync(0xffffffffu, s0, 16);
                float r1 = __shfl_xor_sync(0xffffffffu, s1, 16);
                fin0 = (jb1 ? kk[2] : kk[0]) + r0;
                fin1 = (jb1 ? kk[3] : kk[1]) + r1;
            }
            const int lj = (tid >> 3) & 3;
            *(float2*)&s_part[wid][l * 8 + lj * 2] = make_float2(fin0, fin1);
        }
        __syncthreads();

        if (act && tid < 64) {
            float o = s_part[0][tid] + s_part[1][tid] + s_part[2][tid] + s_part[3][tid];
            out[(long long)i * 64 + tid] = o;
        }
    }
}

// ---------------------------------------------------------------------------
extern "C" void kernel_launch(void* const* d_in, const int* in_sizes, int n_in,
                              void* d_out, int out_size)
{
    const float* p   = (const float*)d_in[0];
    const float* x   = (const float*)d_in[1];
    const int*   idx = (const int*)  d_in[2];
    const float* Wq  = (const float*)d_in[3];
    const float* bq  = (const float*)d_in[4];
    const float* Wk  = (const float*)d_in[5];
    const float* bk  = (const float*)d_in[6];
    const float* Wv  = (const float*)d_in[7];
    const float* bv  = (const float*)d_in[8];
    const float* Wp1 = (const float*)d_in[9];
    const float* bp1 = (const float*)d_in[10];
    const float* gp  = (const float*)d_in[11];
    const float* bpv = (const float*)d_in[12];
    const float* Wp2 = (const float*)d_in[13];
    const float* bp2 = (const float*)d_in[14];
    const float* g1  = (const float*)d_in[15];
    const float* bb1 = (const float*)d_in[16];
    const float* Wa  = (const float*)d_in[17];
    const float* ba  = (const float*)d_in[18];
    const float* g2  = (const float*)d_in[19];
    const float* bb2 = (const float*)d_in[20];
    const float* Wb  = (const float*)d_in[21];
    const float* bw  = (const float*)d_in[22];
    float* out = (float*)d_out;

    int N = in_sizes[1] / C;
    if (N > MAXN) N = MAXN;

    qkv_mma<<<(N + QR - 1) / QR, 256>>>(x, p, Wq, bq, Wk, bk, Wv, bv, N);

    pt_attn<<<(N + PTS - 1) / PTS, 128>>>(idx, Wp1, bp1, gp, bpv, Wp2, bp2,
                                          g1, bb1, Wa, ba, g2, bb2, Wb, bw, out, N);
}